// round 14
// baseline (speedup 1.0000x reference)
#include <cuda_runtime.h>
#include <cuda_fp16.h>

#define B_    64
#define S_    512
#define H_    128
#define NH_   4
#define NHH_  512
#define QSCALE 0.08838834764831845f   /* 1/sqrt(128) */
#define LOG2E_ 1.4426950408889634f
#define NEG_INF_ -1e9f

// ---------------- packed fp16 scratch ----------------------------------------
// "Unit" = float2 (8B) = 2 half2: unit u holds (h2[j], h2[j+4]) with
// j = 8*(u>>2) + (u&3).  h2[j] = (T[2j], T[2j+1]) along the MMA k-dim.
__device__ float2 g_Qh [(size_t)B_ * NH_ * S_ * 32];      // [bh][s][32u]  (Q scaled by QSCALE*log2e)
__device__ float2 g_Kh [(size_t)B_ * NH_ * S_ * 32];      // [bh][s][32u]
__device__ float2 g_Vth[(size_t)B_ * NH_ * H_ * 4 * 32];  // [bh][d][kt4][32u] (128 kv/tile)
__device__ float2 g_ctxh[(size_t)B_ * S_ * 4 * 32];       // [tok][kc4][32u]
__device__ float2 g_Wh [3 * 512 * 32];                    // [mat][n][32u], Wq*QSCALE*log2e folded
__device__ float2 g_Woh[128 * 4 * 32];                    // [n][kc4][32u]

// ---------------- helpers ----------------------------------------------------
__device__ __forceinline__ unsigned h2u(float x, float y) {
    __half2 h = __floats2half2_rn(x, y);
    return *reinterpret_cast<unsigned*>(&h);
}
__device__ __forceinline__ unsigned hh2u(__half x, __half y) {
    __half2 h = __halves2half2(x, y);
    return *reinterpret_cast<unsigned*>(&h);
}
__device__ __forceinline__ unsigned fu(float x) { return __float_as_uint(x); }
__device__ __forceinline__ float    uf(unsigned u) { return __uint_as_float(u); }

__device__ __forceinline__ void mma_f16(float c[4],
                                        unsigned a0, unsigned a1, unsigned a2, unsigned a3,
                                        unsigned b0, unsigned b1) {
    asm volatile(
        "mma.sync.aligned.m16n8k16.row.col.f32.f16.f16.f32 "
        "{%0,%1,%2,%3}, {%4,%5,%6,%7}, {%8,%9}, {%0,%1,%2,%3};"
        : "+f"(c[0]), "+f"(c[1]), "+f"(c[2]), "+f"(c[3])
        : "r"(a0), "r"(a1), "r"(a2), "r"(a3), "r"(b0), "r"(b1));
}

__device__ __forceinline__ void cpa16(void* dst, const void* src) {
    unsigned d = (unsigned)__cvta_generic_to_shared(dst);
    asm volatile("cp.async.cg.shared.global [%0], [%1], 16;" :: "r"(d), "l"(src));
}
__device__ __forceinline__ void cp_commit() { asm volatile("cp.async.commit_group;"); }
template<int N> __device__ __forceinline__ void cp_wait() {
    asm volatile("cp.async.wait_group %0;" :: "n"(N));
}

// =============================================================================
// Kernel 0: pack weights to fp16 packed-unit layout. 65536 threads.
// Wq gets QSCALE*LOG2E folded (scores emerge in log2 domain).
// =============================================================================
__global__ void __launch_bounds__(256) prep_kernel(
    const float* __restrict__ Wq, const float* __restrict__ Wk,
    const float* __restrict__ Wv, const float* __restrict__ Wo)
{
    int idx = blockIdx.x * 256 + threadIdx.x;
    if (idx < 3 * 512 * 32) {
        int u = idx & 31, n = (idx >> 5) & 511, mat = idx >> 14;
        const float* W = (mat == 0) ? Wq : (mat == 1) ? Wk : Wv;
        float scl = (mat == 0) ? QSCALE * LOG2E_ : 1.0f;
        int j = 8 * (u >> 2) + (u & 3);
        float2 v;
        v.x = uf(h2u(W[(size_t)(2 * j)     * NHH_ + n] * scl,
                     W[(size_t)(2 * j + 1) * NHH_ + n] * scl));
        v.y = uf(h2u(W[(size_t)(2 * j + 8) * NHH_ + n] * scl,
                     W[(size_t)(2 * j + 9) * NHH_ + n] * scl));
        g_Wh[idx] = v;
    } else {
        int i2 = idx - 3 * 512 * 32;
        int u = i2 & 31, kc = (i2 >> 5) & 3, n = i2 >> 7;
        int j = 8 * (u >> 2) + (u & 3);
        int kb = kc * 128;
        float2 v;
        v.x = uf(h2u(Wo[(size_t)(kb + 2 * j)     * H_ + n],
                     Wo[(size_t)(kb + 2 * j + 1) * H_ + n]));
        v.y = uf(h2u(Wo[(size_t)(kb + 2 * j + 8) * H_ + n],
                     Wo[(size_t)(kb + 2 * j + 9) * H_ + n]));
        g_Woh[(size_t)(n * 4 + kc) * 32 + u] = v;
    }
}

// =============================================================================
// Kernel 1: QKV projection, m-resident, fp16 MMA, double-buffered W prefetch.
// (verified R9/R10 version)
// =============================================================================
__global__ void __launch_bounds__(256, 2) qkv_kernel(const float* __restrict__ enc)
{
    extern __shared__ float sm[];
    float2* Ap  = (float2*)sm;              // [0,4608)
    float2* Ws0 = (float2*)(sm + 4608);     // [4608,13824)
    float2* Ws1 = (float2*)(sm + 13824);    // [13824,23040)
    __half* Vst = (__half*)(sm + 23040);    // 64x132 halfs (16896 B)

    const int tid = threadIdx.x, lane = tid & 31, wid = tid >> 5;
    const int gid = lane >> 2, tig = lane & 3;
    const int mw = wid & 1, nw = wid >> 1;
    const int m0 = blockIdx.x * 64;
    const int r0 = mw * 32 + gid;
    __half2* Aph2 = (__half2*)Ap;

#pragma unroll
    for (int t = 0; t < 8; t++) {
        int idx = tid + t * 256;
        int r = idx >> 5, sl = idx & 31;
        float4 a = *(const float4*)&enc[(size_t)(m0 + r) * H_ + sl * 4];
        int j0 = 2 * sl, j1 = 2 * sl + 1;
        int u0 = 4 * (j0 >> 3) + (j0 & 3), c0 = (j0 >> 2) & 1;
        int u1 = 4 * (j1 >> 3) + (j1 & 3), c1 = (j1 >> 2) & 1;
        Aph2[(r * 36 + u0) * 2 + c0] = __floats2half2_rn(a.x, a.y);
        Aph2[(r * 36 + u1) * 2 + c1] = __floats2half2_rn(a.z, a.w);
    }

#pragma unroll
    for (int t = 0; t < 8; t++) {
        int idx = tid + t * 256;
        int r = idx >> 4, q = idx & 15;
        cpa16(&Ws0[r * 36 + 2 * q], &g_Wh[(size_t)(r << 5) + 2 * q]);
    }
    cp_commit();

    for (int ch = 0; ch < 12; ch++) {
        const int mat = ch >> 2, hq = ch & 3;
        float2* Wb = (ch & 1) ? Ws1 : Ws0;
        float2* Wn = (ch & 1) ? Ws0 : Ws1;

        __syncthreads();
        if (ch < 11) {
            const int nm = (ch + 1) >> 2, nh = (ch + 1) & 3;
#pragma unroll
            for (int t = 0; t < 8; t++) {
                int idx = tid + t * 256;
                int r = idx >> 4, q = idx & 15;
                cpa16(&Wn[r * 36 + 2 * q],
                      &g_Wh[(size_t)((nm * 512 + nh * 128 + r) << 5) + 2 * q]);
            }
            cp_commit();
            cp_wait<1>();
        } else {
            cp_wait<0>();
        }
        __syncthreads();

        float c[2][4][4];
#pragma unroll
        for (int mt = 0; mt < 2; mt++)
#pragma unroll
            for (int nt = 0; nt < 4; nt++)
#pragma unroll
                for (int j = 0; j < 4; j++) c[mt][nt][j] = 0.0f;

#pragma unroll
        for (int s2 = 0; s2 < 8; s2++) {
            float2 A0  = Ap[(r0)      * 36 + 4 * s2 + tig];
            float2 A8  = Ap[(r0 + 8)  * 36 + 4 * s2 + tig];
            float2 A16 = Ap[(r0 + 16) * 36 + 4 * s2 + tig];
            float2 A24 = Ap[(r0 + 24) * 36 + 4 * s2 + tig];
#pragma unroll
            for (int nt = 0; nt < 4; nt++) {
                float2 Bv = Wb[(nw * 32 + nt * 8 + gid) * 36 + 4 * s2 + tig];
                mma_f16(c[0][nt], fu(A0.x),  fu(A8.x),  fu(A0.y),  fu(A8.y),  fu(Bv.x), fu(Bv.y));
                mma_f16(c[1][nt], fu(A16.x), fu(A24.x), fu(A16.y), fu(A24.y), fu(Bv.x), fu(Bv.y));
            }
        }

        if (mat < 2) {
            float2* dst = (mat == 0) ? g_Qh : g_Kh;
#pragma unroll
            for (int mt = 0; mt < 2; mt++)
#pragma unroll
                for (int hf = 0; hf < 2; hf++) {
                    int rr = mw * 32 + mt * 16 + hf * 8 + gid;
                    int tok = m0 + rr, bbv = tok >> 9, srow = tok & 511;
                    size_t base = ((size_t)(bbv * NH_ + hq) * S_ + srow) * 32;
#pragma unroll
                    for (int p = 0; p < 2; p++) {
                        float2 v;
                        v.x = uf(h2u(c[mt][2 * p][hf * 2],     c[mt][2 * p][hf * 2 + 1]));
                        v.y = uf(h2u(c[mt][2 * p + 1][hf * 2], c[mt][2 * p + 1][hf * 2 + 1]));
                        dst[base + 8 * nw + 4 * p + tig] = v;
                    }
                }
        } else {
            __syncthreads();
#pragma unroll
            for (int mt = 0; mt < 2; mt++)
#pragma unroll
                for (int hf = 0; hf < 2; hf++) {
                    int rr = mw * 32 + mt * 16 + hf * 8 + gid;
#pragma unroll
                    for (int nt = 0; nt < 4; nt++) {
                        int jd = 16 * nw + 4 * nt + tig;
                        *(__half2*)&Vst[rr * 132 + 2 * jd] =
                            __floats2half2_rn(c[mt][nt][hf * 2], c[mt][nt][hf * 2 + 1]);
                    }
                }
            __syncthreads();
            const int bbv = m0 >> 9;
            const int kt4 = (m0 & 511) >> 7;
            const int hi  = (m0 >> 6) & 1;
            size_t vbase = (size_t)(bbv * NH_ + hq) * H_;
#pragma unroll
            for (int t = 0; t < 8; t++) {
                int idx = tid + t * 256;
                int d = idx >> 4, ul = idx & 15;
                int j0l = 8 * (ul >> 2) + (ul & 3);
                float2 o;
                o.x = uf(hh2u(Vst[(2 * j0l)     * 132 + d], Vst[(2 * j0l + 1) * 132 + d]));
                o.y = uf(hh2u(Vst[(2 * j0l + 8) * 132 + d], Vst[(2 * j0l + 9) * 132 + d]));
                g_Vth[((vbase + d) * 4 + kt4) * 32 + 16 * hi + ul] = o;
            }
        }
    }
}

// =============================================================================
// Kernel 2: FA2 flash attention, K-TILE 64, 2 CTAs/SM, exp2-domain softmax.
// Q-tile 128, 8 warps; each warp owns 16 q-rows x full 64-k width.
// Softmax warp-local, P in registers.  8 kt iters, double-buffered K/V.
// smem 114688 B: Qh 128x36u, Kb0/1 64x36u, Vb0/1 128x20u.
// =============================================================================
__global__ void __launch_bounds__(256, 2) attn_kernel(const int* __restrict__ mask)
{
    extern __shared__ float sm[];
    float2* Qh  = (float2*)sm;               // 128x36u  floats [0,9216)
    float2* Kb0 = (float2*)(sm + 9216);      // 64x36u   [9216,13824)
    float2* Kb1 = (float2*)(sm + 13824);     // [13824,18432)
    float2* Vb0 = (float2*)(sm + 18432);     // 128x20u  [18432,23552)
    float2* Vb1 = (float2*)(sm + 23552);     // [23552,28672)

    const int tid = threadIdx.x, lane = tid & 31, wq = tid >> 5;
    const int gid = lane >> 2, tig = lane & 3;
    const int q0 = blockIdx.x * 128;
    const int hq = blockIdx.y, bb = blockIdx.z;
    const int bh = bb * NH_ + hq;
    const int r0 = wq * 16 + gid;
    const int gq0 = q0 + r0, gq1 = gq0 + 8;

    // prefetch Q + K tile 0 + V tile 0
#pragma unroll
    for (int t = 0; t < 8; t++) {
        int idx = tid + t * 256;
        int r = idx >> 4, q = idx & 15;
        cpa16(&Qh[r * 36 + 2 * q], &g_Qh[((size_t)bh * S_ + q0 + r) * 32 + 2 * q]);
    }
#pragma unroll
    for (int t = 0; t < 4; t++) {
        int idx = tid + t * 256;
        int r = idx >> 4, q = idx & 15;
        cpa16(&Kb0[r * 36 + 2 * q], &g_Kh[((size_t)bh * S_ + r) * 32 + 2 * q]);
    }
#pragma unroll
    for (int t = 0; t < 4; t++) {
        int idx = tid + t * 256;
        int d = idx >> 3, q = idx & 7;
        cpa16(&Vb0[d * 20 + 2 * q], &g_Vth[(((size_t)bh * H_ + d) * 4) * 32 + 2 * q]);
    }
    cp_commit();

    float O[16][4];
#pragma unroll
    for (int nt = 0; nt < 16; nt++)
#pragma unroll
        for (int j = 0; j < 4; j++) O[nt][j] = 0.0f;
    float m0v = -1e30f, m1v = -1e30f, l0 = 0.0f, l1 = 0.0f;

    for (int kt = 0; kt < 8; kt++) {
        float2* Kc = (kt & 1) ? Kb1 : Kb0;
        float2* Vc = (kt & 1) ? Vb1 : Vb0;
        float2* Kn = (kt & 1) ? Kb0 : Kb1;
        float2* Vn = (kt & 1) ? Vb0 : Vb1;
        const int k0 = kt * 64;

        __syncthreads();                     // all warps done reading Kn/Vn
        if (kt < 7) {
            const int kn0 = k0 + 64;
#pragma unroll
            for (int t = 0; t < 4; t++) {
                int idx = tid + t * 256;
                int r = idx >> 4, q = idx & 15;
                cpa16(&Kn[r * 36 + 2 * q],
                      &g_Kh[((size_t)bh * S_ + kn0 + r) * 32 + 2 * q]);
            }
#pragma unroll
            for (int t = 0; t < 4; t++) {
                int idx = tid + t * 256;
                int d = idx >> 3, q = idx & 7;
                cpa16(&Vn[d * 20 + 2 * q],
                      &g_Vth[(((size_t)bh * H_ + d) * 4 + ((kt + 1) >> 1)) * 32
                             + 16 * ((kt + 1) & 1) + 2 * q]);
            }
            cp_commit();
            cp_wait<1>();                    // tile kt complete
        } else {
            cp_wait<0>();
        }
        __syncthreads();                     // tile kt visible

        // ---- S = Q K^T (log2-domain scores: Q pre-scaled by QSCALE*log2e) ----
        float c[8][4];
#pragma unroll
        for (int nt = 0; nt < 8; nt++)
#pragma unroll
            for (int j = 0; j < 4; j++) c[nt][j] = 0.0f;
#pragma unroll
        for (int s2 = 0; s2 < 8; s2++) {
            float2 A0 = Qh[(r0)     * 36 + 4 * s2 + tig];
            float2 A8 = Qh[(r0 + 8) * 36 + 4 * s2 + tig];
#pragma unroll
            for (int nt = 0; nt < 8; nt++) {
                float2 Bv = Kc[(8 * nt + gid) * 36 + 4 * s2 + tig];
                mma_f16(c[nt], fu(A0.x), fu(A8.x), fu(A0.y), fu(A8.y), fu(Bv.x), fu(Bv.y));
            }
        }

        // ---- mask + row max (warp-local) ----
        float mx0 = -1e30f, mx1 = -1e30f;
#pragma unroll
        for (int nt = 0; nt < 8; nt++) {
            int kc = k0 + 8 * nt + 2 * tig;
            int2 mk0 = *(const int2*)&mask[((size_t)bb * S_ + gq0) * S_ + kc];
            int2 mk1 = *(const int2*)&mask[((size_t)bb * S_ + gq1) * S_ + kc];
            if (mk0.x == 0) c[nt][0] = NEG_INF_;
            if (mk0.y == 0) c[nt][1] = NEG_INF_;
            if (mk1.x == 0) c[nt][2] = NEG_INF_;
            if (mk1.y == 0) c[nt][3] = NEG_INF_;
            mx0 = fmaxf(mx0, fmaxf(c[nt][0], c[nt][1]));
            mx1 = fmaxf(mx1, fmaxf(c[nt][2], c[nt][3]));
        }
        mx0 = fmaxf(mx0, __shfl_xor_sync(0xffffffffu, mx0, 1));
        mx0 = fmaxf(mx0, __shfl_xor_sync(0xffffffffu, mx0, 2));
        mx1 = fmaxf(mx1, __shfl_xor_sync(0xffffffffu, mx1, 1));
        mx1 = fmaxf(mx1, __shfl_xor_sync(0xffffffffu, mx1, 2));

        float nm0 = fmaxf(m0v, mx0), nm1 = fmaxf(m1v, mx1);
        float al0 = exp2f(m0v - nm0), al1 = exp2f(m1v - nm1);
        m0v = nm0; m1v = nm1;

        float s0 = 0.0f, s1 = 0.0f;
#pragma unroll
        for (int nt = 0; nt < 8; nt++) {
            c[nt][0] = exp2f(c[nt][0] - nm0);
            c[nt][1] = exp2f(c[nt][1] - nm0);
            c[nt][2] = exp2f(c[nt][2] - nm1);
            c[nt][3] = exp2f(c[nt][3] - nm1);
            s0 += c[nt][0] + c[nt][1];
            s1 += c[nt][2] + c[nt][3];
        }
        s0 += __shfl_xor_sync(0xffffffffu, s0, 1);
        s0 += __shfl_xor_sync(0xffffffffu, s0, 2);
        s1 += __shfl_xor_sync(0xffffffffu, s1, 1);
        s1 += __shfl_xor_sync(0xffffffffu, s1, 2);
        l0 = l0 * al0 + s0;
        l1 = l1 * al1 + s1;

#pragma unroll
        for (int nt = 0; nt < 16; nt++) {
            O[nt][0] *= al0; O[nt][1] *= al0;
            O[nt][2] *= al1; O[nt][3] *= al1;
        }

        // ---- O += P @ V : P from c-frags (c[2p],c[2p+1] = a-frag of k-step p) ----
#pragma unroll
        for (int p = 0; p < 4; p++) {
            unsigned pa0 = h2u(c[2 * p][0],     c[2 * p][1]);
            unsigned pa1 = h2u(c[2 * p][2],     c[2 * p][3]);
            unsigned pa2 = h2u(c[2 * p + 1][0], c[2 * p + 1][1]);
            unsigned pa3 = h2u(c[2 * p + 1][2], c[2 * p + 1][3]);
#pragma unroll
            for (int ntd = 0; ntd < 16; ntd++) {
                float2 Bv = Vc[(8 * ntd + gid) * 20 + 4 * p + tig];
                mma_f16(O[ntd], pa0, pa1, pa2, pa3, fu(Bv.x), fu(Bv.y));
            }
        }
    }

    // ---- normalize, pack ctx units ----
    float inv0 = 1.0f / l0, inv1 = 1.0f / l1;
    size_t cb0 = ((size_t)(bb * S_ + gq0) * 4 + hq) * 32;
    size_t cb1 = ((size_t)(bb * S_ + gq1) * 4 + hq) * 32;
#pragma unroll
    for (int p = 0; p < 8; p++) {
        float2 v0, v1;
        v0.x = uf(h2u(O[2 * p][0] * inv0,     O[2 * p][1] * inv0));
        v0.y = uf(h2u(O[2 * p + 1][0] * inv0, O[2 * p + 1][1] * inv0));
        v1.x = uf(h2u(O[2 * p][2] * inv1,     O[2 * p][3] * inv1));
        v1.y = uf(h2u(O[2 * p + 1][2] * inv1, O[2 * p + 1][3] * inv1));
        g_ctxh[cb0 + 4 * p + tig] = v0;
        g_ctxh[cb1 + 4 * p + tig] = v1;
    }
}

// =============================================================================
// Kernel 3: out = ctx @ Wo + enc, LayerNorm.  (unchanged, verified)
// =============================================================================
__global__ void __launch_bounds__(256, 2) out_kernel(
    const float* __restrict__ enc, const float* __restrict__ gamma,
    const float* __restrict__ beta, float* __restrict__ out)
{
    extern __shared__ float sm[];
    float2* Ap0 = (float2*)sm;
    float2* Ap1 = (float2*)(sm + 4608);
    float2* Ws0 = (float2*)(sm + 9216);
    float2* Ws1 = (float2*)(sm + 18432);
    float*  Cs  = sm;

    const int tid = threadIdx.x, lane = tid & 31, wid = tid >> 5;
    const int gid = lane >> 2, tig = lane & 3;
    const int mw = wid & 1, nw = wid >> 1;
    const int m0 = blockIdx.x * 64;
    const int r0 = mw * 32 + gid;

#pragma unroll
    for (int t = 0; t < 4; t++) {
        int idx = tid + t * 256;
        int r = idx >> 4, q = idx & 15;
        cpa16(&Ap0[r * 36 + 2 * q], &g_ctxh[((size_t)(m0 + r) * 4) * 32 + 2 * q]);
    }
#pragma unroll
    for (int t = 0; t < 8; t++) {
        int idx = tid + t * 256;
        int r = idx >> 4, q = idx & 15;
        cpa16(&Ws0[r * 36 + 2 * q], &g_Woh[((size_t)r * 4) * 32 + 2 * q]);
    }
    cp_commit();

    float c[2][4][4];
#pragma unroll
    for (int mt = 0; mt < 2; mt++)
#pragma unroll
        for (int nt = 0; nt < 4; nt++)
#pragma unroll
            for (int j = 0; j < 4; j++) c[mt][nt][j] = 0.0f;

    for (int kc = 0; kc < 4; kc++) {
        float2* Ab = (kc & 1) ? Ap1 : Ap0;
        float2* Wb = (kc & 1) ? Ws1 : Ws0;
        float2* An = (kc & 1) ? Ap0 : Ap1;
        float2* Wn = (kc & 1) ? Ws0 : Ws1;

        __syncthreads();
        if (kc < 3) {
#pragma unroll
            for (int t = 0; t < 4; t++) {
                int idx = tid + t * 256;
                int r = idx >> 4, q = idx & 15;
                cpa16(&An[r * 36 + 2 * q],
                      &g_ctxh[((size_t)(m0 + r) * 4 + kc + 1) * 32 + 2 * q]);
            }
#pragma unroll
            for (int t = 0; t < 8; t++) {
                int idx = tid + t * 256;
                int r = idx >> 4, q = idx & 15;
                cpa16(&Wn[r * 36 + 2 * q],
                      &g_Woh[((size_t)r * 4 + kc + 1) * 32 + 2 * q]);
            }
            cp_commit();
            cp_wait<1>();
        } else {
            cp_wait<0>();
        }
        __syncthreads();

#pragma unroll
        for (int s2 = 0; s2 < 8; s2++) {
            float2 A0  = Ab[(r0)      * 36 + 4 * s2 + tig];
            float2 A8  = Ab[(r0 + 8)  * 36 + 4 * s2 + tig];
            float2 A16 = Ab[(r0 + 16) * 36 + 4 * s2 + tig];
            float2 A24 = Ab[(r0 + 24) * 36 + 4 * s2 + tig];
#pragma unroll
            for (int nt = 0; nt < 4; nt++) {
                float2 Bv = Wb[(nw * 32 + nt * 8 + gid) * 36 + 4 * s2 + tig];
                mma_f16(c[0][nt], fu(A0.x),  fu(A8.x),  fu(A0.y),  fu(A8.y),  fu(Bv.x), fu(Bv.y));
                mma_f16(c[1][nt], fu(A16.x), fu(A24.x), fu(A16.y), fu(A24.y), fu(Bv.x), fu(Bv.y));
            }
        }
    }
    __syncthreads();

#pragma unroll
    for (int mt = 0; mt < 2; mt++)
#pragma unroll
        for (int hf = 0; hf < 2; hf++) {
            int rr = mw * 32 + mt * 16 + hf * 8 + gid;
#pragma unroll
            for (int nt = 0; nt < 4; nt++) {
                int col = nw * 32 + nt * 8 + 2 * tig;
                *(float2*)&Cs[rr * 132 + col] =
                    make_float2(c[mt][nt][hf * 2 + 0], c[mt][nt][hf * 2 + 1]);
            }
        }
    __syncthreads();

    const int row = tid >> 2, q = tid & 3;
    float x[32];
    float ssum = 0.0f, ssq = 0.0f;
#pragma unroll
    for (int i = 0; i < 8; i++) {
        float4 v = *(float4*)&Cs[row * 132 + q * 32 + i * 4];
        float4 e = *(const float4*)&enc[(size_t)(m0 + row) * H_ + q * 32 + i * 4];
        x[4 * i + 0] = v.x + e.x; x[4 * i + 1] = v.y + e.y;
        x[4 * i + 2] = v.z + e.z; x[4 * i + 3] = v.w + e.w;
#pragma unroll
        for (int j = 0; j < 4; j++) {
            ssum += x[4 * i + j];
            ssq  += x[4 * i + j] * x[4 * i + j];
        }
    }
    ssum += __shfl_xor_sync(0xffffffffu, ssum, 1);
    ssum += __shfl_xor_sync(0xffffffffu, ssum, 2);
    ssq  += __shfl_xor_sync(0xffffffffu, ssq,  1);
    ssq  += __shfl_xor_sync(0xffffffffu, ssq,  2);
    float mean = ssum * (1.0f / 128.0f);
    float var  = ssq * (1.0f / 128.0f) - mean * mean;
    float rstd = rsqrtf(var + 1e-6f);

#pragma unroll
    for (int i = 0; i < 8; i++) {
        float4 g  = *(const float4*)&gamma[q * 32 + i * 4];
        float4 be = *(const float4*)&beta[q * 32 + i * 4];
        float4 y = make_float4((x[4 * i + 0] - mean) * rstd * g.x + be.x,
                               (x[4 * i + 1] - mean) * rstd * g.y + be.y,
                               (x[4 * i + 2] - mean) * rstd * g.z + be.z,
                               (x[4 * i + 3] - mean) * rstd * g.w + be.w);
        *(float4*)&out[(size_t)(m0 + row) * H_ + q * 32 + i * 4] = y;
    }
}

// =============================================================================
extern "C" void kernel_launch(void* const* d_in, const int* in_sizes, int n_in,
                              void* d_out, int out_size)
{
    const float* enc   = (const float*)d_in[0];
    const int*   mask  = (const int*)  d_in[1];
    const float* Wq    = (const float*)d_in[2];
    const float* Wk    = (const float*)d_in[3];
    const float* Wv    = (const float*)d_in[4];
    const float* Wo    = (const float*)d_in[5];
    const float* gamma = (const float*)d_in[6];
    const float* beta  = (const float*)d_in[7];
    float* out = (float*)d_out;

    prep_kernel<<<256, 256>>>(Wq, Wk, Wv, Wo);

    const int smem1 = 109056;
    cudaFuncSetAttribute(qkv_kernel, cudaFuncAttributeMaxDynamicSharedMemorySize, smem1);
    qkv_kernel<<<(B_ * S_) / 64, 256, smem1>>>(enc);

    const int smem2 = 114688;
    cudaFuncSetAttribute(attn_kernel, cudaFuncAttributeMaxDynamicSharedMemorySize, smem2);
    dim3 g2(S_ / 128, NH_, B_);
    attn_kernel<<<g2, 256, smem2>>>(mask);

    const int smem3 = 110592;
    cudaFuncSetAttribute(out_kernel, cudaFuncAttributeMaxDynamicSharedMemorySize, smem3);
    out_kernel<<<(B_ * S_) / 64, 256, smem3>>>(enc, gamma, beta, out);
}

// round 15
// speedup vs baseline: 1.4851x; 1.4851x over previous
#include <cuda_runtime.h>
#include <cuda_fp16.h>

#define B_    64
#define S_    512
#define H_    128
#define NH_   4
#define NHH_  512
#define QSCALE 0.08838834764831845f   /* 1/sqrt(128) */
#define LOG2E_ 1.4426950408889634f
#define NEG_INF_ -1e9f

// ---------------- packed fp16 scratch ----------------------------------------
// "Unit" = float2 (8B) = 2 half2: unit u holds (h2[j], h2[j+4]) with
// j = 8*(u>>2) + (u&3).  h2[j] = (T[2j], T[2j+1]) along the MMA k-dim.
__device__ float2 g_Qh [(size_t)B_ * NH_ * S_ * 32];      // [bh][s][32u]  (Q scaled by QSCALE*log2e)
__device__ float2 g_Kh [(size_t)B_ * NH_ * S_ * 32];      // [bh][s][32u]
__device__ float2 g_Vth[(size_t)B_ * NH_ * H_ * 4 * 32];  // [bh][d][kt4][32u] (128 kv/tile)
__device__ float2 g_ctxh[(size_t)B_ * S_ * 4 * 32];       // [tok][kc4][32u]
__device__ float2 g_Wh [3 * 512 * 32];                    // [mat][n][32u], Wq*QSCALE*log2e folded
__device__ float2 g_Woh[128 * 4 * 32];                    // [n][kc4][32u]

// ---------------- helpers ----------------------------------------------------
__device__ __forceinline__ unsigned h2u(float x, float y) {
    __half2 h = __floats2half2_rn(x, y);
    return *reinterpret_cast<unsigned*>(&h);
}
__device__ __forceinline__ unsigned hh2u(__half x, __half y) {
    __half2 h = __halves2half2(x, y);
    return *reinterpret_cast<unsigned*>(&h);
}
__device__ __forceinline__ unsigned fu(float x) { return __float_as_uint(x); }
__device__ __forceinline__ float    uf(unsigned u) { return __uint_as_float(u); }

__device__ __forceinline__ void mma_f16(float c[4],
                                        unsigned a0, unsigned a1, unsigned a2, unsigned a3,
                                        unsigned b0, unsigned b1) {
    asm volatile(
        "mma.sync.aligned.m16n8k16.row.col.f32.f16.f16.f32 "
        "{%0,%1,%2,%3}, {%4,%5,%6,%7}, {%8,%9}, {%0,%1,%2,%3};"
        : "+f"(c[0]), "+f"(c[1]), "+f"(c[2]), "+f"(c[3])
        : "r"(a0), "r"(a1), "r"(a2), "r"(a3), "r"(b0), "r"(b1));
}

__device__ __forceinline__ void cpa16(void* dst, const void* src) {
    unsigned d = (unsigned)__cvta_generic_to_shared(dst);
    asm volatile("cp.async.cg.shared.global [%0], [%1], 16;" :: "r"(d), "l"(src));
}
__device__ __forceinline__ void cp_commit() { asm volatile("cp.async.commit_group;"); }
template<int N> __device__ __forceinline__ void cp_wait() {
    asm volatile("cp.async.wait_group %0;" :: "n"(N));
}

// =============================================================================
// Kernel 0: pack weights to fp16 packed-unit layout. 65536 threads.
// Wq gets QSCALE*LOG2E folded (scores emerge in log2 domain).
// =============================================================================
__global__ void __launch_bounds__(256) prep_kernel(
    const float* __restrict__ Wq, const float* __restrict__ Wk,
    const float* __restrict__ Wv, const float* __restrict__ Wo)
{
    int idx = blockIdx.x * 256 + threadIdx.x;
    if (idx < 3 * 512 * 32) {
        int u = idx & 31, n = (idx >> 5) & 511, mat = idx >> 14;
        const float* W = (mat == 0) ? Wq : (mat == 1) ? Wk : Wv;
        float scl = (mat == 0) ? QSCALE * LOG2E_ : 1.0f;
        int j = 8 * (u >> 2) + (u & 3);
        float2 v;
        v.x = uf(h2u(W[(size_t)(2 * j)     * NHH_ + n] * scl,
                     W[(size_t)(2 * j + 1) * NHH_ + n] * scl));
        v.y = uf(h2u(W[(size_t)(2 * j + 8) * NHH_ + n] * scl,
                     W[(size_t)(2 * j + 9) * NHH_ + n] * scl));
        g_Wh[idx] = v;
    } else {
        int i2 = idx - 3 * 512 * 32;
        int u = i2 & 31, kc = (i2 >> 5) & 3, n = i2 >> 7;
        int j = 8 * (u >> 2) + (u & 3);
        int kb = kc * 128;
        float2 v;
        v.x = uf(h2u(Wo[(size_t)(kb + 2 * j)     * H_ + n],
                     Wo[(size_t)(kb + 2 * j + 1) * H_ + n]));
        v.y = uf(h2u(Wo[(size_t)(kb + 2 * j + 8) * H_ + n],
                     Wo[(size_t)(kb + 2 * j + 9) * H_ + n]));
        g_Woh[(size_t)(n * 4 + kc) * 32 + u] = v;
    }
}

// =============================================================================
// Kernel 1: QKV projection, m-resident, fp16 MMA, double-buffered W prefetch.
// (verified R9/R10 version)
// =============================================================================
__global__ void __launch_bounds__(256, 2) qkv_kernel(const float* __restrict__ enc)
{
    extern __shared__ float sm[];
    float2* Ap  = (float2*)sm;              // [0,4608)
    float2* Ws0 = (float2*)(sm + 4608);     // [4608,13824)
    float2* Ws1 = (float2*)(sm + 13824);    // [13824,23040)
    __half* Vst = (__half*)(sm + 23040);    // 64x132 halfs (16896 B)

    const int tid = threadIdx.x, lane = tid & 31, wid = tid >> 5;
    const int gid = lane >> 2, tig = lane & 3;
    const int mw = wid & 1, nw = wid >> 1;
    const int m0 = blockIdx.x * 64;
    const int r0 = mw * 32 + gid;
    __half2* Aph2 = (__half2*)Ap;

#pragma unroll
    for (int t = 0; t < 8; t++) {
        int idx = tid + t * 256;
        int r = idx >> 5, sl = idx & 31;
        float4 a = *(const float4*)&enc[(size_t)(m0 + r) * H_ + sl * 4];
        int j0 = 2 * sl, j1 = 2 * sl + 1;
        int u0 = 4 * (j0 >> 3) + (j0 & 3), c0 = (j0 >> 2) & 1;
        int u1 = 4 * (j1 >> 3) + (j1 & 3), c1 = (j1 >> 2) & 1;
        Aph2[(r * 36 + u0) * 2 + c0] = __floats2half2_rn(a.x, a.y);
        Aph2[(r * 36 + u1) * 2 + c1] = __floats2half2_rn(a.z, a.w);
    }

#pragma unroll
    for (int t = 0; t < 8; t++) {
        int idx = tid + t * 256;
        int r = idx >> 4, q = idx & 15;
        cpa16(&Ws0[r * 36 + 2 * q], &g_Wh[(size_t)(r << 5) + 2 * q]);
    }
    cp_commit();

    for (int ch = 0; ch < 12; ch++) {
        const int mat = ch >> 2, hq = ch & 3;
        float2* Wb = (ch & 1) ? Ws1 : Ws0;
        float2* Wn = (ch & 1) ? Ws0 : Ws1;

        __syncthreads();
        if (ch < 11) {
            const int nm = (ch + 1) >> 2, nh = (ch + 1) & 3;
#pragma unroll
            for (int t = 0; t < 8; t++) {
                int idx = tid + t * 256;
                int r = idx >> 4, q = idx & 15;
                cpa16(&Wn[r * 36 + 2 * q],
                      &g_Wh[(size_t)((nm * 512 + nh * 128 + r) << 5) + 2 * q]);
            }
            cp_commit();
            cp_wait<1>();
        } else {
            cp_wait<0>();
        }
        __syncthreads();

        float c[2][4][4];
#pragma unroll
        for (int mt = 0; mt < 2; mt++)
#pragma unroll
            for (int nt = 0; nt < 4; nt++)
#pragma unroll
                for (int j = 0; j < 4; j++) c[mt][nt][j] = 0.0f;

#pragma unroll
        for (int s2 = 0; s2 < 8; s2++) {
            float2 A0  = Ap[(r0)      * 36 + 4 * s2 + tig];
            float2 A8  = Ap[(r0 + 8)  * 36 + 4 * s2 + tig];
            float2 A16 = Ap[(r0 + 16) * 36 + 4 * s2 + tig];
            float2 A24 = Ap[(r0 + 24) * 36 + 4 * s2 + tig];
#pragma unroll
            for (int nt = 0; nt < 4; nt++) {
                float2 Bv = Wb[(nw * 32 + nt * 8 + gid) * 36 + 4 * s2 + tig];
                mma_f16(c[0][nt], fu(A0.x),  fu(A8.x),  fu(A0.y),  fu(A8.y),  fu(Bv.x), fu(Bv.y));
                mma_f16(c[1][nt], fu(A16.x), fu(A24.x), fu(A16.y), fu(A24.y), fu(Bv.x), fu(Bv.y));
            }
        }

        if (mat < 2) {
            float2* dst = (mat == 0) ? g_Qh : g_Kh;
#pragma unroll
            for (int mt = 0; mt < 2; mt++)
#pragma unroll
                for (int hf = 0; hf < 2; hf++) {
                    int rr = mw * 32 + mt * 16 + hf * 8 + gid;
                    int tok = m0 + rr, bbv = tok >> 9, srow = tok & 511;
                    size_t base = ((size_t)(bbv * NH_ + hq) * S_ + srow) * 32;
#pragma unroll
                    for (int p = 0; p < 2; p++) {
                        float2 v;
                        v.x = uf(h2u(c[mt][2 * p][hf * 2],     c[mt][2 * p][hf * 2 + 1]));
                        v.y = uf(h2u(c[mt][2 * p + 1][hf * 2], c[mt][2 * p + 1][hf * 2 + 1]));
                        dst[base + 8 * nw + 4 * p + tig] = v;
                    }
                }
        } else {
            __syncthreads();
#pragma unroll
            for (int mt = 0; mt < 2; mt++)
#pragma unroll
                for (int hf = 0; hf < 2; hf++) {
                    int rr = mw * 32 + mt * 16 + hf * 8 + gid;
#pragma unroll
                    for (int nt = 0; nt < 4; nt++) {
                        int jd = 16 * nw + 4 * nt + tig;
                        *(__half2*)&Vst[rr * 132 + 2 * jd] =
                            __floats2half2_rn(c[mt][nt][hf * 2], c[mt][nt][hf * 2 + 1]);
                    }
                }
            __syncthreads();
            const int bbv = m0 >> 9;
            const int kt4 = (m0 & 511) >> 7;
            const int hi  = (m0 >> 6) & 1;
            size_t vbase = (size_t)(bbv * NH_ + hq) * H_;
#pragma unroll
            for (int t = 0; t < 8; t++) {
                int idx = tid + t * 256;
                int d = idx >> 4, ul = idx & 15;
                int j0l = 8 * (ul >> 2) + (ul & 3);
                float2 o;
                o.x = uf(hh2u(Vst[(2 * j0l)     * 132 + d], Vst[(2 * j0l + 1) * 132 + d]));
                o.y = uf(hh2u(Vst[(2 * j0l + 8) * 132 + d], Vst[(2 * j0l + 9) * 132 + d]));
                g_Vth[((vbase + d) * 4 + kt4) * 32 + 16 * hi + ul] = o;
            }
        }
    }
}

// =============================================================================
// Kernel 2: FA2 flash attention, K-TILE 64, 2 CTAs/SM, exp2-domain softmax.
// Q-tile 128, 8 warps; each warp owns 16 q-rows x full 64-k width.
// Softmax warp-local, P in registers.  8 kt iters, double-buffered K/V.
// smem 114688 B: Qh 128x36u, Kb0/1 64x36u, Vb0/1 128x20u.
// =============================================================================
__global__ void __launch_bounds__(256, 2) attn_kernel(const int* __restrict__ mask)
{
    extern __shared__ float sm[];
    float2* Qh  = (float2*)sm;               // 128x36u  floats [0,9216)
    float2* Kb0 = (float2*)(sm + 9216);      // 64x36u   [9216,13824)
    float2* Kb1 = (float2*)(sm + 13824);     // [13824,18432)
    float2* Vb0 = (float2*)(sm + 18432);     // 128x20u  [18432,23552)
    float2* Vb1 = (float2*)(sm + 23552);     // [23552,28672)

    const int tid = threadIdx.x, lane = tid & 31, wq = tid >> 5;
    const int gid = lane >> 2, tig = lane & 3;
    const int q0 = blockIdx.x * 128;
    const int hq = blockIdx.y, bb = blockIdx.z;
    const int bh = bb * NH_ + hq;
    const int r0 = wq * 16 + gid;
    const int gq0 = q0 + r0, gq1 = gq0 + 8;

    // prefetch Q + K tile 0 + V tile 0
#pragma unroll
    for (int t = 0; t < 8; t++) {
        int idx = tid + t * 256;
        int r = idx >> 4, q = idx & 15;
        cpa16(&Qh[r * 36 + 2 * q], &g_Qh[((size_t)bh * S_ + q0 + r) * 32 + 2 * q]);
    }
#pragma unroll
    for (int t = 0; t < 4; t++) {
        int idx = tid + t * 256;
        int r = idx >> 4, q = idx & 15;
        cpa16(&Kb0[r * 36 + 2 * q], &g_Kh[((size_t)bh * S_ + r) * 32 + 2 * q]);
    }
#pragma unroll
    for (int t = 0; t < 4; t++) {
        int idx = tid + t * 256;
        int d = idx >> 3, q = idx & 7;
        cpa16(&Vb0[d * 20 + 2 * q], &g_Vth[(((size_t)bh * H_ + d) * 4) * 32 + 2 * q]);
    }
    cp_commit();

    float O[16][4];
#pragma unroll
    for (int nt = 0; nt < 16; nt++)
#pragma unroll
        for (int j = 0; j < 4; j++) O[nt][j] = 0.0f;
    float m0v = -1e30f, m1v = -1e30f, l0 = 0.0f, l1 = 0.0f;

    for (int kt = 0; kt < 8; kt++) {
        float2* Kc = (kt & 1) ? Kb1 : Kb0;
        float2* Vc = (kt & 1) ? Vb1 : Vb0;
        float2* Kn = (kt & 1) ? Kb0 : Kb1;
        float2* Vn = (kt & 1) ? Vb0 : Vb1;
        const int k0 = kt * 64;

        __syncthreads();                     // all warps done reading Kn/Vn
        if (kt < 7) {
            const int kn0 = k0 + 64;
#pragma unroll
            for (int t = 0; t < 4; t++) {
                int idx = tid + t * 256;
                int r = idx >> 4, q = idx & 15;
                cpa16(&Kn[r * 36 + 2 * q],
                      &g_Kh[((size_t)bh * S_ + kn0 + r) * 32 + 2 * q]);
            }
#pragma unroll
            for (int t = 0; t < 4; t++) {
                int idx = tid + t * 256;
                int d = idx >> 3, q = idx & 7;
                cpa16(&Vn[d * 20 + 2 * q],
                      &g_Vth[(((size_t)bh * H_ + d) * 4 + ((kt + 1) >> 1)) * 32
                             + 16 * ((kt + 1) & 1) + 2 * q]);
            }
            cp_commit();
            cp_wait<1>();                    // tile kt complete
        } else {
            cp_wait<0>();
        }
        __syncthreads();                     // tile kt visible

        // ---- S = Q K^T (log2-domain scores: Q pre-scaled by QSCALE*log2e) ----
        float c[8][4];
#pragma unroll
        for (int nt = 0; nt < 8; nt++)
#pragma unroll
            for (int j = 0; j < 4; j++) c[nt][j] = 0.0f;
#pragma unroll
        for (int s2 = 0; s2 < 8; s2++) {
            float2 A0 = Qh[(r0)     * 36 + 4 * s2 + tig];
            float2 A8 = Qh[(r0 + 8) * 36 + 4 * s2 + tig];
#pragma unroll
            for (int nt = 0; nt < 8; nt++) {
                float2 Bv = Kc[(8 * nt + gid) * 36 + 4 * s2 + tig];
                mma_f16(c[nt], fu(A0.x), fu(A8.x), fu(A0.y), fu(A8.y), fu(Bv.x), fu(Bv.y));
            }
        }

        // ---- mask + row max (warp-local) ----
        float mx0 = -1e30f, mx1 = -1e30f;
#pragma unroll
        for (int nt = 0; nt < 8; nt++) {
            int kc = k0 + 8 * nt + 2 * tig;
            int2 mk0 = *(const int2*)&mask[((size_t)bb * S_ + gq0) * S_ + kc];
            int2 mk1 = *(const int2*)&mask[((size_t)bb * S_ + gq1) * S_ + kc];
            if (mk0.x == 0) c[nt][0] = NEG_INF_;
            if (mk0.y == 0) c[nt][1] = NEG_INF_;
            if (mk1.x == 0) c[nt][2] = NEG_INF_;
            if (mk1.y == 0) c[nt][3] = NEG_INF_;
            mx0 = fmaxf(mx0, fmaxf(c[nt][0], c[nt][1]));
            mx1 = fmaxf(mx1, fmaxf(c[nt][2], c[nt][3]));
        }
        mx0 = fmaxf(mx0, __shfl_xor_sync(0xffffffffu, mx0, 1));
        mx0 = fmaxf(mx0, __shfl_xor_sync(0xffffffffu, mx0, 2));
        mx1 = fmaxf(mx1, __shfl_xor_sync(0xffffffffu, mx1, 1));
        mx1 = fmaxf(mx1, __shfl_xor_sync(0xffffffffu, mx1, 2));

        float nm0 = fmaxf(m0v, mx0), nm1 = fmaxf(m1v, mx1);
        float al0 = exp2f(m0v - nm0), al1 = exp2f(m1v - nm1);
        m0v = nm0; m1v = nm1;

        float s0 = 0.0f, s1 = 0.0f;
#pragma unroll
        for (int nt = 0; nt < 8; nt++) {
            c[nt][0] = exp2f(c[nt][0] - nm0);
            c[nt][1] = exp2f(c[nt][1] - nm0);
            c[nt][2] = exp2f(c[nt][2] - nm1);
            c[nt][3] = exp2f(c[nt][3] - nm1);
            s0 += c[nt][0] + c[nt][1];
            s1 += c[nt][2] + c[nt][3];
        }
        s0 += __shfl_xor_sync(0xffffffffu, s0, 1);
        s0 += __shfl_xor_sync(0xffffffffu, s0, 2);
        s1 += __shfl_xor_sync(0xffffffffu, s1, 1);
        s1 += __shfl_xor_sync(0xffffffffu, s1, 2);
        l0 = l0 * al0 + s0;
        l1 = l1 * al1 + s1;

#pragma unroll
        for (int nt = 0; nt < 16; nt++) {
            O[nt][0] *= al0; O[nt][1] *= al0;
            O[nt][2] *= al1; O[nt][3] *= al1;
        }

        // ---- O += P @ V : P from c-frags (c[2p],c[2p+1] = a-frag of k-step p) ----
#pragma unroll
        for (int p = 0; p < 4; p++) {
            unsigned pa0 = h2u(c[2 * p][0],     c[2 * p][1]);
            unsigned pa1 = h2u(c[2 * p][2],     c[2 * p][3]);
            unsigned pa2 = h2u(c[2 * p + 1][0], c[2 * p + 1][1]);
            unsigned pa3 = h2u(c[2 * p + 1][2], c[2 * p + 1][3]);
#pragma unroll
            for (int ntd = 0; ntd < 16; ntd++) {
                float2 Bv = Vc[(8 * ntd + gid) * 20 + 4 * p + tig];
                mma_f16(O[ntd], pa0, pa1, pa2, pa3, fu(Bv.x), fu(Bv.y));
            }
        }
    }

    // ---- normalize, pack ctx units ----
    float inv0 = 1.0f / l0, inv1 = 1.0f / l1;
    size_t cb0 = ((size_t)(bb * S_ + gq0) * 4 + hq) * 32;
    size_t cb1 = ((size_t)(bb * S_ + gq1) * 4 + hq) * 32;
#pragma unroll
    for (int p = 0; p < 8; p++) {
        float2 v0, v1;
        v0.x = uf(h2u(O[2 * p][0] * inv0,     O[2 * p][1] * inv0));
        v0.y = uf(h2u(O[2 * p + 1][0] * inv0, O[2 * p + 1][1] * inv0));
        v1.x = uf(h2u(O[2 * p][2] * inv1,     O[2 * p][3] * inv1));
        v1.y = uf(h2u(O[2 * p + 1][2] * inv1, O[2 * p + 1][3] * inv1));
        g_ctxh[cb0 + 4 * p + tig] = v0;
        g_ctxh[cb1 + 4 * p + tig] = v1;
    }
}

// =============================================================================
// Kernel 3: out = ctx @ Wo + enc, LayerNorm.  (unchanged, verified)
// =============================================================================
__global__ void __launch_bounds__(256, 2) out_kernel(
    const float* __restrict__ enc, const float* __restrict__ gamma,
    const float* __restrict__ beta, float* __restrict__ out)
{
    extern __shared__ float sm[];
    float2* Ap0 = (float2*)sm;
    float2* Ap1 = (float2*)(sm + 4608);
    float2* Ws0 = (float2*)(sm + 9216);
    float2* Ws1 = (float2*)(sm + 18432);
    float*  Cs  = sm;

    const int tid = threadIdx.x, lane = tid & 31, wid = tid >> 5;
    const int gid = lane >> 2, tig = lane & 3;
    const int mw = wid & 1, nw = wid >> 1;
    const int m0 = blockIdx.x * 64;
    const int r0 = mw * 32 + gid;

#pragma unroll
    for (int t = 0; t < 4; t++) {
        int idx = tid + t * 256;
        int r = idx >> 4, q = idx & 15;
        cpa16(&Ap0[r * 36 + 2 * q], &g_ctxh[((size_t)(m0 + r) * 4) * 32 + 2 * q]);
    }
#pragma unroll
    for (int t = 0; t < 8; t++) {
        int idx = tid + t * 256;
        int r = idx >> 4, q = idx & 15;
        cpa16(&Ws0[r * 36 + 2 * q], &g_Woh[((size_t)r * 4) * 32 + 2 * q]);
    }
    cp_commit();

    float c[2][4][4];
#pragma unroll
    for (int mt = 0; mt < 2; mt++)
#pragma unroll
        for (int nt = 0; nt < 4; nt++)
#pragma unroll
            for (int j = 0; j < 4; j++) c[mt][nt][j] = 0.0f;

    for (int kc = 0; kc < 4; kc++) {
        float2* Ab = (kc & 1) ? Ap1 : Ap0;
        float2* Wb = (kc & 1) ? Ws1 : Ws0;
        float2* An = (kc & 1) ? Ap0 : Ap1;
        float2* Wn = (kc & 1) ? Ws0 : Ws1;

        __syncthreads();
        if (kc < 3) {
#pragma unroll
            for (int t = 0; t < 4; t++) {
                int idx = tid + t * 256;
                int r = idx >> 4, q = idx & 15;
                cpa16(&An[r * 36 + 2 * q],
                      &g_ctxh[((size_t)(m0 + r) * 4 + kc + 1) * 32 + 2 * q]);
            }
#pragma unroll
            for (int t = 0; t < 8; t++) {
                int idx = tid + t * 256;
                int r = idx >> 4, q = idx & 15;
                cpa16(&Wn[r * 36 + 2 * q],
                      &g_Woh[((size_t)r * 4 + kc + 1) * 32 + 2 * q]);
            }
            cp_commit();
            cp_wait<1>();
        } else {
            cp_wait<0>();
        }
        __syncthreads();

#pragma unroll
        for (int s2 = 0; s2 < 8; s2++) {
            float2 A0  = Ab[(r0)      * 36 + 4 * s2 + tig];
            float2 A8  = Ab[(r0 + 8)  * 36 + 4 * s2 + tig];
            float2 A16 = Ab[(r0 + 16) * 36 + 4 * s2 + tig];
            float2 A24 = Ab[(r0 + 24) * 36 + 4 * s2 + tig];
#pragma unroll
            for (int nt = 0; nt < 4; nt++) {
                float2 Bv = Wb[(nw * 32 + nt * 8 + gid) * 36 + 4 * s2 + tig];
                mma_f16(c[0][nt], fu(A0.x),  fu(A8.x),  fu(A0.y),  fu(A8.y),  fu(Bv.x), fu(Bv.y));
                mma_f16(c[1][nt], fu(A16.x), fu(A24.x), fu(A16.y), fu(A24.y), fu(Bv.x), fu(Bv.y));
            }
        }
    }
    __syncthreads();

#pragma unroll
    for (int mt = 0; mt < 2; mt++)
#pragma unroll
        for (int hf = 0; hf < 2; hf++) {
            int rr = mw * 32 + mt * 16 + hf * 8 + gid;
#pragma unroll
            for (int nt = 0; nt < 4; nt++) {
                int col = nw * 32 + nt * 8 + 2 * tig;
                *(float2*)&Cs[rr * 132 + col] =
                    make_float2(c[mt][nt][hf * 2 + 0], c[mt][nt][hf * 2 + 1]);
            }
        }
    __syncthreads();

    const int row = tid >> 2, q = tid & 3;
    float x[32];
    float ssum = 0.0f, ssq = 0.0f;
#pragma unroll
    for (int i = 0; i < 8; i++) {
        float4 v = *(float4*)&Cs[row * 132 + q * 32 + i * 4];
        float4 e = *(const float4*)&enc[(size_t)(m0 + row) * H_ + q * 32 + i * 4];
        x[4 * i + 0] = v.x + e.x; x[4 * i + 1] = v.y + e.y;
        x[4 * i + 2] = v.z + e.z; x[4 * i + 3] = v.w + e.w;
#pragma unroll
        for (int j = 0; j < 4; j++) {
            ssum += x[4 * i + j];
            ssq  += x[4 * i + j] * x[4 * i + j];
        }
    }
    ssum += __shfl_xor_sync(0xffffffffu, ssum, 1);
    ssum += __shfl_xor_sync(0xffffffffu, ssum, 2);
    ssq  += __shfl_xor_sync(0xffffffffu, ssq,  1);
    ssq  += __shfl_xor_sync(0xffffffffu, ssq,  2);
    float mean = ssum * (1.0f / 128.0f);
    float var  = ssq * (1.0f / 128.0f) - mean * mean;
    float rstd = rsqrtf(var + 1e-6f);

#pragma unroll
    for (int i = 0; i < 8; i++) {
        float4 g  = *(const float4*)&gamma[q * 32 + i * 4];
        float4 be = *(const float4*)&beta[q * 32 + i * 4];
        float4 y = make_float4((x[4 * i + 0] - mean) * rstd * g.x + be.x,
                               (x[4 * i + 1] - mean) * rstd * g.y + be.y,
                               (x[4 * i + 2] - mean) * rstd * g.z + be.z,
                               (x[4 * i + 3] - mean) * rstd * g.w + be.w);
        *(float4*)&out[(size_t)(m0 + row) * H_ + q * 32 + i * 4] = y;
    }
}

// =============================================================================
extern "C" void kernel_launch(void* const* d_in, const int* in_sizes, int n_in,
                              void* d_out, int out_size)
{
    const float* enc   = (const float*)d_in[0];
    const int*   mask  = (const int*)  d_in[1];
    const float* Wq    = (const float*)d_in[2];
    const float* Wk    = (const float*)d_in[3];
    const float* Wv    = (const float*)d_in[4];
    const float* Wo    = (const float*)d_in[5];
    const float* gamma = (const float*)d_in[6];
    const float* beta  = (const float*)d_in[7];
    float* out = (float*)d_out;

    prep_kernel<<<256, 256>>>(Wq, Wk, Wv, Wo);

    const int smem1 = 109056;
    cudaFuncSetAttribute(qkv_kernel, cudaFuncAttributeMaxDynamicSharedMemorySize, smem1);
    qkv_kernel<<<(B_ * S_) / 64, 256, smem1>>>(enc);

    const int smem2 = 114688;
    cudaFuncSetAttribute(attn_kernel, cudaFuncAttributeMaxDynamicSharedMemorySize, smem2);
    dim3 g2(S_ / 128, NH_, B_);
    attn_kernel<<<g2, 256, smem2>>>(mask);

    const int smem3 = 110592;
    cudaFuncSetAttribute(out_kernel, cudaFuncAttributeMaxDynamicSharedMemorySize, smem3);
    out_kernel<<<(B_ * S_) / 64, 256, smem3>>>(enc, gamma, beta, out);
}

// round 16
// speedup vs baseline: 1.4979x; 1.0086x over previous
#include <cuda_runtime.h>
#include <cuda_fp16.h>

#define B_    64
#define S_    512
#define H_    128
#define NH_   4
#define NHH_  512
#define QSCALE 0.08838834764831845f   /* 1/sqrt(128) */
#define LOG2E_ 1.4426950408889634f
#define NEG_INF_ -1e9f

// ---------------- packed fp16 scratch ----------------------------------------
// "Unit" = float2 (8B) = 2 half2: unit u holds (h2[j], h2[j+4]) with
// j = 8*(u>>2) + (u&3).  h2[j] = (T[2j], T[2j+1]) along the MMA k-dim.
__device__ float2 g_Qh [(size_t)B_ * NH_ * S_ * 32];      // [bh][s][32u]  (Q scaled by QSCALE*log2e)
__device__ float2 g_Kh [(size_t)B_ * NH_ * S_ * 32];      // [bh][s][32u]
__device__ float2 g_Vth[(size_t)B_ * NH_ * H_ * 4 * 32];  // [bh][d][kt4][32u] (128 kv/tile)
__device__ float2 g_ctxh[(size_t)B_ * S_ * 4 * 32];       // [tok][kc4][32u]
__device__ float2 g_Wh [3 * 512 * 32];                    // [mat][n][32u], Wq*QSCALE*log2e folded
__device__ float2 g_Woh[128 * 4 * 32];                    // [n][kc4][32u]

// ---------------- helpers ----------------------------------------------------
__device__ __forceinline__ unsigned h2u(float x, float y) {
    __half2 h = __floats2half2_rn(x, y);
    return *reinterpret_cast<unsigned*>(&h);
}
__device__ __forceinline__ unsigned hh2u(__half x, __half y) {
    __half2 h = __halves2half2(x, y);
    return *reinterpret_cast<unsigned*>(&h);
}
__device__ __forceinline__ unsigned fu(float x) { return __float_as_uint(x); }
__device__ __forceinline__ float    uf(unsigned u) { return __uint_as_float(u); }

// fp16x2 exp2: one MUFU-class op for two probabilities, output IS the PV a-frag half.
__device__ __forceinline__ unsigned ex2h2(float x, float y) {
    __half2 h = __floats2half2_rn(x, y);
    unsigned u = *reinterpret_cast<unsigned*>(&h);
    asm("ex2.approx.f16x2 %0, %0;" : "+r"(u));
    return u;
}
__device__ __forceinline__ float2 uh2f2(unsigned u) {
    __half2 h = *reinterpret_cast<__half2*>(&u);
    return __half22float2(h);
}

__device__ __forceinline__ void mma_f16(float c[4],
                                        unsigned a0, unsigned a1, unsigned a2, unsigned a3,
                                        unsigned b0, unsigned b1) {
    asm volatile(
        "mma.sync.aligned.m16n8k16.row.col.f32.f16.f16.f32 "
        "{%0,%1,%2,%3}, {%4,%5,%6,%7}, {%8,%9}, {%0,%1,%2,%3};"
        : "+f"(c[0]), "+f"(c[1]), "+f"(c[2]), "+f"(c[3])
        : "r"(a0), "r"(a1), "r"(a2), "r"(a3), "r"(b0), "r"(b1));
}

__device__ __forceinline__ void cpa16(void* dst, const void* src) {
    unsigned d = (unsigned)__cvta_generic_to_shared(dst);
    asm volatile("cp.async.cg.shared.global [%0], [%1], 16;" :: "r"(d), "l"(src));
}
__device__ __forceinline__ void cp_commit() { asm volatile("cp.async.commit_group;"); }
template<int N> __device__ __forceinline__ void cp_wait() {
    asm volatile("cp.async.wait_group %0;" :: "n"(N));
}

// =============================================================================
// Kernel 0: pack weights to fp16 packed-unit layout. 65536 threads.
// Wq gets QSCALE*LOG2E folded (scores emerge in log2 domain).
// =============================================================================
__global__ void __launch_bounds__(256) prep_kernel(
    const float* __restrict__ Wq, const float* __restrict__ Wk,
    const float* __restrict__ Wv, const float* __restrict__ Wo)
{
    int idx = blockIdx.x * 256 + threadIdx.x;
    if (idx < 3 * 512 * 32) {
        int u = idx & 31, n = (idx >> 5) & 511, mat = idx >> 14;
        const float* W = (mat == 0) ? Wq : (mat == 1) ? Wk : Wv;
        float scl = (mat == 0) ? QSCALE * LOG2E_ : 1.0f;
        int j = 8 * (u >> 2) + (u & 3);
        float2 v;
        v.x = uf(h2u(W[(size_t)(2 * j)     * NHH_ + n] * scl,
                     W[(size_t)(2 * j + 1) * NHH_ + n] * scl));
        v.y = uf(h2u(W[(size_t)(2 * j + 8) * NHH_ + n] * scl,
                     W[(size_t)(2 * j + 9) * NHH_ + n] * scl));
        g_Wh[idx] = v;
    } else {
        int i2 = idx - 3 * 512 * 32;
        int u = i2 & 31, kc = (i2 >> 5) & 3, n = i2 >> 7;
        int j = 8 * (u >> 2) + (u & 3);
        int kb = kc * 128;
        float2 v;
        v.x = uf(h2u(Wo[(size_t)(kb + 2 * j)     * H_ + n],
                     Wo[(size_t)(kb + 2 * j + 1) * H_ + n]));
        v.y = uf(h2u(Wo[(size_t)(kb + 2 * j + 8) * H_ + n],
                     Wo[(size_t)(kb + 2 * j + 9) * H_ + n]));
        g_Woh[(size_t)(n * 4 + kc) * 32 + u] = v;
    }
}

// =============================================================================
// Kernel 1: QKV projection, m-resident, fp16 MMA, double-buffered W prefetch.
// (verified R9/R10 version)
// =============================================================================
__global__ void __launch_bounds__(256, 2) qkv_kernel(const float* __restrict__ enc)
{
    extern __shared__ float sm[];
    float2* Ap  = (float2*)sm;              // [0,4608)
    float2* Ws0 = (float2*)(sm + 4608);     // [4608,13824)
    float2* Ws1 = (float2*)(sm + 13824);    // [13824,23040)
    __half* Vst = (__half*)(sm + 23040);    // 64x132 halfs (16896 B)

    const int tid = threadIdx.x, lane = tid & 31, wid = tid >> 5;
    const int gid = lane >> 2, tig = lane & 3;
    const int mw = wid & 1, nw = wid >> 1;
    const int m0 = blockIdx.x * 64;
    const int r0 = mw * 32 + gid;
    __half2* Aph2 = (__half2*)Ap;

#pragma unroll
    for (int t = 0; t < 8; t++) {
        int idx = tid + t * 256;
        int r = idx >> 5, sl = idx & 31;
        float4 a = *(const float4*)&enc[(size_t)(m0 + r) * H_ + sl * 4];
        int j0 = 2 * sl, j1 = 2 * sl + 1;
        int u0 = 4 * (j0 >> 3) + (j0 & 3), c0 = (j0 >> 2) & 1;
        int u1 = 4 * (j1 >> 3) + (j1 & 3), c1 = (j1 >> 2) & 1;
        Aph2[(r * 36 + u0) * 2 + c0] = __floats2half2_rn(a.x, a.y);
        Aph2[(r * 36 + u1) * 2 + c1] = __floats2half2_rn(a.z, a.w);
    }

#pragma unroll
    for (int t = 0; t < 8; t++) {
        int idx = tid + t * 256;
        int r = idx >> 4, q = idx & 15;
        cpa16(&Ws0[r * 36 + 2 * q], &g_Wh[(size_t)(r << 5) + 2 * q]);
    }
    cp_commit();

    for (int ch = 0; ch < 12; ch++) {
        const int mat = ch >> 2, hq = ch & 3;
        float2* Wb = (ch & 1) ? Ws1 : Ws0;
        float2* Wn = (ch & 1) ? Ws0 : Ws1;

        __syncthreads();
        if (ch < 11) {
            const int nm = (ch + 1) >> 2, nh = (ch + 1) & 3;
#pragma unroll
            for (int t = 0; t < 8; t++) {
                int idx = tid + t * 256;
                int r = idx >> 4, q = idx & 15;
                cpa16(&Wn[r * 36 + 2 * q],
                      &g_Wh[(size_t)((nm * 512 + nh * 128 + r) << 5) + 2 * q]);
            }
            cp_commit();
            cp_wait<1>();
        } else {
            cp_wait<0>();
        }
        __syncthreads();

        float c[2][4][4];
#pragma unroll
        for (int mt = 0; mt < 2; mt++)
#pragma unroll
            for (int nt = 0; nt < 4; nt++)
#pragma unroll
                for (int j = 0; j < 4; j++) c[mt][nt][j] = 0.0f;

#pragma unroll
        for (int s2 = 0; s2 < 8; s2++) {
            float2 A0  = Ap[(r0)      * 36 + 4 * s2 + tig];
            float2 A8  = Ap[(r0 + 8)  * 36 + 4 * s2 + tig];
            float2 A16 = Ap[(r0 + 16) * 36 + 4 * s2 + tig];
            float2 A24 = Ap[(r0 + 24) * 36 + 4 * s2 + tig];
#pragma unroll
            for (int nt = 0; nt < 4; nt++) {
                float2 Bv = Wb[(nw * 32 + nt * 8 + gid) * 36 + 4 * s2 + tig];
                mma_f16(c[0][nt], fu(A0.x),  fu(A8.x),  fu(A0.y),  fu(A8.y),  fu(Bv.x), fu(Bv.y));
                mma_f16(c[1][nt], fu(A16.x), fu(A24.x), fu(A16.y), fu(A24.y), fu(Bv.x), fu(Bv.y));
            }
        }

        if (mat < 2) {
            float2* dst = (mat == 0) ? g_Qh : g_Kh;
#pragma unroll
            for (int mt = 0; mt < 2; mt++)
#pragma unroll
                for (int hf = 0; hf < 2; hf++) {
                    int rr = mw * 32 + mt * 16 + hf * 8 + gid;
                    int tok = m0 + rr, bbv = tok >> 9, srow = tok & 511;
                    size_t base = ((size_t)(bbv * NH_ + hq) * S_ + srow) * 32;
#pragma unroll
                    for (int p = 0; p < 2; p++) {
                        float2 v;
                        v.x = uf(h2u(c[mt][2 * p][hf * 2],     c[mt][2 * p][hf * 2 + 1]));
                        v.y = uf(h2u(c[mt][2 * p + 1][hf * 2], c[mt][2 * p + 1][hf * 2 + 1]));
                        dst[base + 8 * nw + 4 * p + tig] = v;
                    }
                }
        } else {
            __syncthreads();
#pragma unroll
            for (int mt = 0; mt < 2; mt++)
#pragma unroll
                for (int hf = 0; hf < 2; hf++) {
                    int rr = mw * 32 + mt * 16 + hf * 8 + gid;
#pragma unroll
                    for (int nt = 0; nt < 4; nt++) {
                        int jd = 16 * nw + 4 * nt + tig;
                        *(__half2*)&Vst[rr * 132 + 2 * jd] =
                            __floats2half2_rn(c[mt][nt][hf * 2], c[mt][nt][hf * 2 + 1]);
                    }
                }
            __syncthreads();
            const int bbv = m0 >> 9;
            const int kt4 = (m0 & 511) >> 7;
            const int hi  = (m0 >> 6) & 1;
            size_t vbase = (size_t)(bbv * NH_ + hq) * H_;
#pragma unroll
            for (int t = 0; t < 8; t++) {
                int idx = tid + t * 256;
                int d = idx >> 4, ul = idx & 15;
                int j0l = 8 * (ul >> 2) + (ul & 3);
                float2 o;
                o.x = uf(hh2u(Vst[(2 * j0l)     * 132 + d], Vst[(2 * j0l + 1) * 132 + d]));
                o.y = uf(hh2u(Vst[(2 * j0l + 8) * 132 + d], Vst[(2 * j0l + 9) * 132 + d]));
                g_Vth[((vbase + d) * 4 + kt4) * 32 + 16 * hi + ul] = o;
            }
        }
    }
}

// =============================================================================
// Kernel 2: FA2 flash attention, K-TILE 64, 2 CTAs/SM, fp16x2 exp2 softmax.
// Q-tile 128, 8 warps; each warp owns 16 q-rows x full 64-k width.
// Softmax warp-local, P in registers (fp16x2 straight from ex2.approx.f16x2).
// smem 114688 B: Qh 128x36u, Kb0/1 64x36u, Vb0/1 128x20u.
// =============================================================================
__global__ void __launch_bounds__(256, 2) attn_kernel(const int* __restrict__ mask)
{
    extern __shared__ float sm[];
    float2* Qh  = (float2*)sm;               // 128x36u  floats [0,9216)
    float2* Kb0 = (float2*)(sm + 9216);      // 64x36u   [9216,13824)
    float2* Kb1 = (float2*)(sm + 13824);     // [13824,18432)
    float2* Vb0 = (float2*)(sm + 18432);     // 128x20u  [18432,23552)
    float2* Vb1 = (float2*)(sm + 23552);     // [23552,28672)

    const int tid = threadIdx.x, lane = tid & 31, wq = tid >> 5;
    const int gid = lane >> 2, tig = lane & 3;
    const int q0 = blockIdx.x * 128;
    const int hq = blockIdx.y, bb = blockIdx.z;
    const int bh = bb * NH_ + hq;
    const int r0 = wq * 16 + gid;
    const int gq0 = q0 + r0, gq1 = gq0 + 8;

    // prefetch Q + K tile 0 + V tile 0
#pragma unroll
    for (int t = 0; t < 8; t++) {
        int idx = tid + t * 256;
        int r = idx >> 4, q = idx & 15;
        cpa16(&Qh[r * 36 + 2 * q], &g_Qh[((size_t)bh * S_ + q0 + r) * 32 + 2 * q]);
    }
#pragma unroll
    for (int t = 0; t < 4; t++) {
        int idx = tid + t * 256;
        int r = idx >> 4, q = idx & 15;
        cpa16(&Kb0[r * 36 + 2 * q], &g_Kh[((size_t)bh * S_ + r) * 32 + 2 * q]);
    }
#pragma unroll
    for (int t = 0; t < 4; t++) {
        int idx = tid + t * 256;
        int d = idx >> 3, q = idx & 7;
        cpa16(&Vb0[d * 20 + 2 * q], &g_Vth[(((size_t)bh * H_ + d) * 4) * 32 + 2 * q]);
    }
    cp_commit();

    float O[16][4];
#pragma unroll
    for (int nt = 0; nt < 16; nt++)
#pragma unroll
        for (int j = 0; j < 4; j++) O[nt][j] = 0.0f;
    float m0v = -1e30f, m1v = -1e30f, l0 = 0.0f, l1 = 0.0f;

    for (int kt = 0; kt < 8; kt++) {
        float2* Kc = (kt & 1) ? Kb1 : Kb0;
        float2* Vc = (kt & 1) ? Vb1 : Vb0;
        float2* Kn = (kt & 1) ? Kb0 : Kb1;
        float2* Vn = (kt & 1) ? Vb0 : Vb1;
        const int k0 = kt * 64;

        __syncthreads();                     // all warps done reading Kn/Vn
        if (kt < 7) {
            const int kn0 = k0 + 64;
#pragma unroll
            for (int t = 0; t < 4; t++) {
                int idx = tid + t * 256;
                int r = idx >> 4, q = idx & 15;
                cpa16(&Kn[r * 36 + 2 * q],
                      &g_Kh[((size_t)bh * S_ + kn0 + r) * 32 + 2 * q]);
            }
#pragma unroll
            for (int t = 0; t < 4; t++) {
                int idx = tid + t * 256;
                int d = idx >> 3, q = idx & 7;
                cpa16(&Vn[d * 20 + 2 * q],
                      &g_Vth[(((size_t)bh * H_ + d) * 4 + ((kt + 1) >> 1)) * 32
                             + 16 * ((kt + 1) & 1) + 2 * q]);
            }
            cp_commit();
            cp_wait<1>();                    // tile kt complete
        } else {
            cp_wait<0>();
        }
        __syncthreads();                     // tile kt visible

        // ---- S = Q K^T (log2-domain scores: Q pre-scaled by QSCALE*log2e) ----
        float c[8][4];
#pragma unroll
        for (int nt = 0; nt < 8; nt++)
#pragma unroll
            for (int j = 0; j < 4; j++) c[nt][j] = 0.0f;
#pragma unroll
        for (int s2 = 0; s2 < 8; s2++) {
            float2 A0 = Qh[(r0)     * 36 + 4 * s2 + tig];
            float2 A8 = Qh[(r0 + 8) * 36 + 4 * s2 + tig];
#pragma unroll
            for (int nt = 0; nt < 8; nt++) {
                float2 Bv = Kc[(8 * nt + gid) * 36 + 4 * s2 + tig];
                mma_f16(c[nt], fu(A0.x), fu(A8.x), fu(A0.y), fu(A8.y), fu(Bv.x), fu(Bv.y));
            }
        }

        // ---- mask + row max (warp-local) ----
        float mx0 = -1e30f, mx1 = -1e30f;
#pragma unroll
        for (int nt = 0; nt < 8; nt++) {
            int kc = k0 + 8 * nt + 2 * tig;
            int2 mk0 = *(const int2*)&mask[((size_t)bb * S_ + gq0) * S_ + kc];
            int2 mk1 = *(const int2*)&mask[((size_t)bb * S_ + gq1) * S_ + kc];
            if (mk0.x == 0) c[nt][0] = NEG_INF_;
            if (mk0.y == 0) c[nt][1] = NEG_INF_;
            if (mk1.x == 0) c[nt][2] = NEG_INF_;
            if (mk1.y == 0) c[nt][3] = NEG_INF_;
            mx0 = fmaxf(mx0, fmaxf(c[nt][0], c[nt][1]));
            mx1 = fmaxf(mx1, fmaxf(c[nt][2], c[nt][3]));
        }
        mx0 = fmaxf(mx0, __shfl_xor_sync(0xffffffffu, mx0, 1));
        mx0 = fmaxf(mx0, __shfl_xor_sync(0xffffffffu, mx0, 2));
        mx1 = fmaxf(mx1, __shfl_xor_sync(0xffffffffu, mx1, 1));
        mx1 = fmaxf(mx1, __shfl_xor_sync(0xffffffffu, mx1, 2));

        float nm0 = fmaxf(m0v, mx0), nm1 = fmaxf(m1v, mx1);
        float al0 = exp2f(m0v - nm0), al1 = exp2f(m1v - nm1);
        m0v = nm0; m1v = nm1;

        // ---- exponentials directly in fp16x2: pe[nt][0] = P(r0 pair), [1] = P(r0+8 pair)
        unsigned pe[8][2];
        float s0 = 0.0f, s1 = 0.0f;
#pragma unroll
        for (int nt = 0; nt < 8; nt++) {
            pe[nt][0] = ex2h2(c[nt][0] - nm0, c[nt][1] - nm0);
            pe[nt][1] = ex2h2(c[nt][2] - nm1, c[nt][3] - nm1);
            float2 f0 = uh2f2(pe[nt][0]);
            float2 f1 = uh2f2(pe[nt][1]);
            s0 += f0.x + f0.y;
            s1 += f1.x + f1.y;
        }
        s0 += __shfl_xor_sync(0xffffffffu, s0, 1);
        s0 += __shfl_xor_sync(0xffffffffu, s0, 2);
        s1 += __shfl_xor_sync(0xffffffffu, s1, 1);
        s1 += __shfl_xor_sync(0xffffffffu, s1, 2);
        l0 = l0 * al0 + s0;
        l1 = l1 * al1 + s1;

#pragma unroll
        for (int nt = 0; nt < 16; nt++) {
            O[nt][0] *= al0; O[nt][1] *= al0;
            O[nt][2] *= al1; O[nt][3] *= al1;
        }

        // ---- O += P @ V : pe pairs ARE the a-frags (no packing) ----
#pragma unroll
        for (int p = 0; p < 4; p++) {
            unsigned pa0 = pe[2 * p][0];
            unsigned pa1 = pe[2 * p][1];
            unsigned pa2 = pe[2 * p + 1][0];
            unsigned pa3 = pe[2 * p + 1][1];
#pragma unroll
            for (int ntd = 0; ntd < 16; ntd++) {
                float2 Bv = Vc[(8 * ntd + gid) * 20 + 4 * p + tig];
                mma_f16(O[ntd], pa0, pa1, pa2, pa3, fu(Bv.x), fu(Bv.y));
            }
        }
    }

    // ---- normalize, pack ctx units ----
    float inv0 = 1.0f / l0, inv1 = 1.0f / l1;
    size_t cb0 = ((size_t)(bb * S_ + gq0) * 4 + hq) * 32;
    size_t cb1 = ((size_t)(bb * S_ + gq1) * 4 + hq) * 32;
#pragma unroll
    for (int p = 0; p < 8; p++) {
        float2 v0, v1;
        v0.x = uf(h2u(O[2 * p][0] * inv0,     O[2 * p][1] * inv0));
        v0.y = uf(h2u(O[2 * p + 1][0] * inv0, O[2 * p + 1][1] * inv0));
        v1.x = uf(h2u(O[2 * p][2] * inv1,     O[2 * p][3] * inv1));
        v1.y = uf(h2u(O[2 * p + 1][2] * inv1, O[2 * p + 1][3] * inv1));
        g_ctxh[cb0 + 4 * p + tig] = v0;
        g_ctxh[cb1 + 4 * p + tig] = v1;
    }
}

// =============================================================================
// Kernel 3: out = ctx @ Wo + enc, LayerNorm.  (unchanged, verified)
// =============================================================================
__global__ void __launch_bounds__(256, 2) out_kernel(
    const float* __restrict__ enc, const float* __restrict__ gamma,
    const float* __restrict__ beta, float* __restrict__ out)
{
    extern __shared__ float sm[];
    float2* Ap0 = (float2*)sm;
    float2* Ap1 = (float2*)(sm + 4608);
    float2* Ws0 = (float2*)(sm + 9216);
    float2* Ws1 = (float2*)(sm + 18432);
    float*  Cs  = sm;

    const int tid = threadIdx.x, lane = tid & 31, wid = tid >> 5;
    const int gid = lane >> 2, tig = lane & 3;
    const int mw = wid & 1, nw = wid >> 1;
    const int m0 = blockIdx.x * 64;
    const int r0 = mw * 32 + gid;

#pragma unroll
    for (int t = 0; t < 4; t++) {
        int idx = tid + t * 256;
        int r = idx >> 4, q = idx & 15;
        cpa16(&Ap0[r * 36 + 2 * q], &g_ctxh[((size_t)(m0 + r) * 4) * 32 + 2 * q]);
    }
#pragma unroll
    for (int t = 0; t < 8; t++) {
        int idx = tid + t * 256;
        int r = idx >> 4, q = idx & 15;
        cpa16(&Ws0[r * 36 + 2 * q], &g_Woh[((size_t)r * 4) * 32 + 2 * q]);
    }
    cp_commit();

    float c[2][4][4];
#pragma unroll
    for (int mt = 0; mt < 2; mt++)
#pragma unroll
        for (int nt = 0; nt < 4; nt++)
#pragma unroll
            for (int j = 0; j < 4; j++) c[mt][nt][j] = 0.0f;

    for (int kc = 0; kc < 4; kc++) {
        float2* Ab = (kc & 1) ? Ap1 : Ap0;
        float2* Wb = (kc & 1) ? Ws1 : Ws0;
        float2* An = (kc & 1) ? Ap0 : Ap1;
        float2* Wn = (kc & 1) ? Ws0 : Ws1;

        __syncthreads();
        if (kc < 3) {
#pragma unroll
            for (int t = 0; t < 4; t++) {
                int idx = tid + t * 256;
                int r = idx >> 4, q = idx & 15;
                cpa16(&An[r * 36 + 2 * q],
                      &g_ctxh[((size_t)(m0 + r) * 4 + kc + 1) * 32 + 2 * q]);
            }
#pragma unroll
            for (int t = 0; t < 8; t++) {
                int idx = tid + t * 256;
                int r = idx >> 4, q = idx & 15;
                cpa16(&Wn[r * 36 + 2 * q],
                      &g_Woh[((size_t)r * 4 + kc + 1) * 32 + 2 * q]);
            }
            cp_commit();
            cp_wait<1>();
        } else {
            cp_wait<0>();
        }
        __syncthreads();

#pragma unroll
        for (int s2 = 0; s2 < 8; s2++) {
            float2 A0  = Ab[(r0)      * 36 + 4 * s2 + tig];
            float2 A8  = Ab[(r0 + 8)  * 36 + 4 * s2 + tig];
            float2 A16 = Ab[(r0 + 16) * 36 + 4 * s2 + tig];
            float2 A24 = Ab[(r0 + 24) * 36 + 4 * s2 + tig];
#pragma unroll
            for (int nt = 0; nt < 4; nt++) {
                float2 Bv = Wb[(nw * 32 + nt * 8 + gid) * 36 + 4 * s2 + tig];
                mma_f16(c[0][nt], fu(A0.x),  fu(A8.x),  fu(A0.y),  fu(A8.y),  fu(Bv.x), fu(Bv.y));
                mma_f16(c[1][nt], fu(A16.x), fu(A24.x), fu(A16.y), fu(A24.y), fu(Bv.x), fu(Bv.y));
            }
        }
    }
    __syncthreads();

#pragma unroll
    for (int mt = 0; mt < 2; mt++)
#pragma unroll
        for (int hf = 0; hf < 2; hf++) {
            int rr = mw * 32 + mt * 16 + hf * 8 + gid;
#pragma unroll
            for (int nt = 0; nt < 4; nt++) {
                int col = nw * 32 + nt * 8 + 2 * tig;
                *(float2*)&Cs[rr * 132 + col] =
                    make_float2(c[mt][nt][hf * 2 + 0], c[mt][nt][hf * 2 + 1]);
            }
        }
    __syncthreads();

    const int row = tid >> 2, q = tid & 3;
    float x[32];
    float ssum = 0.0f, ssq = 0.0f;
#pragma unroll
    for (int i = 0; i < 8; i++) {
        float4 v = *(float4*)&Cs[row * 132 + q * 32 + i * 4];
        float4 e = *(const float4*)&enc[(size_t)(m0 + row) * H_ + q * 32 + i * 4];
        x[4 * i + 0] = v.x + e.x; x[4 * i + 1] = v.y + e.y;
        x[4 * i + 2] = v.z + e.z; x[4 * i + 3] = v.w + e.w;
#pragma unroll
        for (int j = 0; j < 4; j++) {
            ssum += x[4 * i + j];
            ssq  += x[4 * i + j] * x[4 * i + j];
        }
    }
    ssum += __shfl_xor_sync(0xffffffffu, ssum, 1);
    ssum += __shfl_xor_sync(0xffffffffu, ssum, 2);
    ssq  += __shfl_xor_sync(0xffffffffu, ssq,  1);
    ssq  += __shfl_xor_sync(0xffffffffu, ssq,  2);
    float mean = ssum * (1.0f / 128.0f);
    float var  = ssq * (1.0f / 128.0f) - mean * mean;
    float rstd = rsqrtf(var + 1e-6f);

#pragma unroll
    for (int i = 0; i < 8; i++) {
        float4 g  = *(const float4*)&gamma[q * 32 + i * 4];
        float4 be = *(const float4*)&beta[q * 32 + i * 4];
        float4 y = make_float4((x[4 * i + 0] - mean) * rstd * g.x + be.x,
                               (x[4 * i + 1] - mean) * rstd * g.y + be.y,
                               (x[4 * i + 2] - mean) * rstd * g.z + be.z,
                               (x[4 * i + 3] - mean) * rstd * g.w + be.w);
        *(float4*)&out[(size_t)(m0 + row) * H_ + q * 32 + i * 4] = y;
    }
}

// =============================================================================
extern "C" void kernel_launch(void* const* d_in, const int* in_sizes, int n_in,
                              void* d_out, int out_size)
{
    const float* enc   = (const float*)d_in[0];
    const int*   mask  = (const int*)  d_in[1];
    const float* Wq    = (const float*)d_in[2];
    const float* Wk    = (const float*)d_in[3];
    const float* Wv    = (const float*)d_in[4];
    const float* Wo    = (const float*)d_in[5];
    const float* gamma = (const float*)d_in[6];
    const float* beta  = (const float*)d_in[7];
    float* out = (float*)d_out;

    prep_kernel<<<256, 256>>>(Wq, Wk, Wv, Wo);

    const int smem1 = 109056;
    cudaFuncSetAttribute(qkv_kernel, cudaFuncAttributeMaxDynamicSharedMemorySize, smem1);
    qkv_kernel<<<(B_ * S_) / 64, 256, smem1>>>(enc);

    const int smem2 = 114688;
    cudaFuncSetAttribute(attn_kernel, cudaFuncAttributeMaxDynamicSharedMemorySize, smem2);
    dim3 g2(S_ / 128, NH_, B_);
    attn_kernel<<<g2, 256, smem2>>>(mask);

    const int smem3 = 110592;
    cudaFuncSetAttribute(out_kernel, cudaFuncAttributeMaxDynamicSharedMemorySize, smem3);
    out_kernel<<<(B_ * S_) / 64, 256, smem3>>>(enc, gamma, beta, out);
}